// round 10
// baseline (speedup 1.0000x reference)
#include <cuda_runtime.h>
#include <math.h>
#include <stdint.h>

#define K_CTX 64
#define D_DIM 128
#define C_CAND 256
#define DS 200
#define EPS 1e-8f
#define GRID_B 128   // 2 candidates per block, concurrent

// Scratch + sync (device globals; no allocation allowed)
__device__ __align__(16) float g_A[K_CTX * D_DIM];
__device__ __align__(16) float g_AM[K_CTX * D_DIM];
__device__ int g_count = 0;   // AM rows produced
__device__ int g_done  = 0;   // blocks finished (reset)

// sB row stride 140 floats (560B, 16B aligned): LDS.128 conflict-free
#define SB_STRIDE 140
#define SB_ROW_BYTES (SB_STRIDE * 4)   // 560
#define SB_FLOATS (K_CTX * SB_STRIDE)  // 8960
// layout: sAM(8192) sB0 sB1 rowsum0/1(128) colsum0/1(128) rows_w0/1(128)
//         cols_w0/1(128) newA0/1(256) newB0/1(256) scratch(1024) scal(8) mbars(8)
#define SMEM_FLOATS (8192 + 2*SB_FLOATS + 128 + 128 + 128 + 128 + 256 + 256 + 1024 + 8 + 8)

__device__ __forceinline__ uint32_t smem_u32(const void* p) {
    return (uint32_t)__cvta_generic_to_shared(p);
}
__device__ __forceinline__ void mbar_init(uint32_t mbar, uint32_t cnt) {
    asm volatile("mbarrier.init.shared.b64 [%0], %1;" :: "r"(mbar), "r"(cnt) : "memory");
}
__device__ __forceinline__ void mbar_expect_tx(uint32_t mbar, uint32_t bytes) {
    asm volatile("mbarrier.arrive.expect_tx.shared.b64 _, [%0], %1;"
                 :: "r"(mbar), "r"(bytes) : "memory");
}
__device__ __forceinline__ void mbar_wait(uint32_t mbar, uint32_t parity) {
    uint32_t done;
    asm volatile(
        "{\n\t.reg .pred p;\n\t"
        "mbarrier.try_wait.parity.acquire.cta.shared::cta.b64 p, [%1], %2;\n\t"
        "selp.b32 %0, 1, 0, p;\n\t}"
        : "=r"(done) : "r"(mbar), "r"(parity) : "memory");
    if (!done) {
        asm volatile(
            "{\n\t.reg .pred P1;\n\t"
            "WAIT_LOOP_%=:\n\t"
            "mbarrier.try_wait.parity.acquire.cta.shared::cta.b64 P1, [%0], %1, 0x989680;\n\t"
            "@P1 bra.uni WAIT_DONE_%=;\n\t"
            "bra.uni WAIT_LOOP_%=;\n\t"
            "WAIT_DONE_%=:\n\t}"
            :: "r"(mbar), "r"(parity) : "memory");
    }
}
__device__ __forceinline__ void bulk_g2s(uint32_t dst_smem, const void* src_gmem,
                                         uint32_t bytes, uint32_t mbar) {
    asm volatile(
        "cp.async.bulk.shared::cluster.global.mbarrier::complete_tx::bytes "
        "[%0], [%1], %2, [%3];"
        :: "r"(dst_smem), "l"(src_gmem), "r"(bytes), "r"(mbar) : "memory");
}
__device__ __forceinline__ float tanh_fast(float x) {
    float y;
    asm("tanh.approx.f32 %0, %1;" : "=f"(y) : "f"(x));
    return y;
}
__device__ __forceinline__ unsigned long long ffma2(unsigned long long a,
                                                    unsigned long long b,
                                                    unsigned long long c) {
    unsigned long long d;
    asm("fma.rn.f32x2 %0, %1, %2, %3;" : "=l"(d) : "l"(a), "l"(b), "l"(c));
    return d;
}
__device__ __forceinline__ float f32x2_hsum(unsigned long long v) {
    float lo = __uint_as_float((unsigned)(v & 0xffffffffull));
    float hi = __uint_as_float((unsigned)(v >> 32));
    return lo + hi;
}

// ---------------------------------------------------------------------------
// grid = 128, block = 512. Block b: candidates c0=2b (warps 0-7), c1=2b+1
// (warps 8-15), sims run CONCURRENTLY. Blocks 0..63 produce one AM row.
// ---------------------------------------------------------------------------
__global__ __launch_bounds__(512, 1)
void cand_kernel(const float* __restrict__ table,
                 const float* __restrict__ str_t1,
                 const float* __restrict__ str_t2s,
                 const float* __restrict__ att_mat,
                 const float* __restrict__ W,     // W_bi[0]: [128,128]
                 const float* __restrict__ b_bi,
                 const int* __restrict__ t1_ctx,
                 const int* __restrict__ t2_ctx,
                 float* __restrict__ out) {
    extern __shared__ __align__(16) float sm[];
    float* sAM     = sm;                          // 8192 (+ producer scratch)
    float* sB0     = sAM + K_CTX * D_DIM;
    float* sB1     = sB0 + SB_FLOATS;
    float* rowsum  = sB1 + SB_FLOATS;             // [2][64]
    float* colsum  = rowsum + 128;                // [2][64]
    float* rows_w  = colsum + 128;                // [2][64]
    float* cols_w  = rows_w + 128;                // [2][64]
    float* newA    = cols_w + 128;                // [2][128]
    float* newB    = newA + 256;                  // [2][128]
    float* scratch = newB + 256;                  // 1024
    float* scal    = scratch + 1024;              // [2][4]
    uint64_t* mbars = (uint64_t*)(scal + 8);      // [0]=g0 [1]=g1 [2]=sAM

    const int b    = blockIdx.x;
    const int c0   = 2 * b;
    const int tid  = threadIdx.x;
    const int wid  = tid >> 5;
    const int lane = tid & 31;
    const int half = wid >> 3;                    // 0 -> c0, 1 -> c1
    const int wloc = wid & 7;                     // warp index within half
    const uint32_t mbar_g0 = smem_u32(&mbars[0]);
    const uint32_t mbar_g1 = smem_u32(&mbars[1]);
    const uint32_t mbar_a  = smem_u32(&mbars[2]);

    // --- phase 0: init mbars + zero accumulators ---
    if (tid == 0) {
        mbar_init(mbar_g0, 1);
        mbar_init(mbar_g1, 1);
        mbar_init(mbar_a, 1);
        mbar_expect_tx(mbar_g0, K_CTX * D_DIM * 4);
        mbar_expect_tx(mbar_g1, K_CTX * D_DIM * 4);
        mbar_expect_tx(mbar_a,  K_CTX * D_DIM * 4);
    }
    if (tid < 128) colsum[tid] = 0.f;
    if (tid < 8) scal[tid] = 0.f;
    __syncthreads();   // mbar init + zeros visible

    // --- phase 1: issue both candidates' B gathers (64 x 512B each) ---
    const int* ctx0 = t2_ctx + c0 * K_CTX;
    const int* ctx1 = ctx0 + K_CTX;
    if (tid < K_CTX) {
        bulk_g2s(smem_u32(sB0) + tid * SB_ROW_BYTES,
                 table + (long long)ctx0[tid] * D_DIM, D_DIM * 4, mbar_g0);
    } else if (tid < 2 * K_CTX) {
        int m = tid - K_CTX;
        bulk_g2s(smem_u32(sB1) + m * SB_ROW_BYTES,
                 table + (long long)ctx1[m] * D_DIM, D_DIM * 4, mbar_g1);
    }

    // --- phase 2: producer — blocks 0..63 compute AM row b (512 threads) ---
    if (b < K_CTX) {
        if (tid < D_DIM) {
            float a = table[(long long)t1_ctx[b] * D_DIM + tid];
            newA[tid] = a;
            g_A[b * D_DIM + tid] = a;
        }
        __syncthreads();
        {
            const int d = tid & 127;
            const int q = tid >> 7;
            const float* att = att_mat + (q * 32) * D_DIM + d;
            const float* ar  = newA + q * 32;
            float acc = 0.f;
#pragma unroll
            for (int e = 0; e < 32; e++)
                acc = fmaf(ar[e], att[e * D_DIM], acc);
            sAM[tid] = acc;
        }
        __syncthreads();
        if (tid < D_DIM) {
            g_AM[b * D_DIM + tid] = sAM[tid] + sAM[D_DIM + tid]
                                  + sAM[2 * D_DIM + tid] + sAM[3 * D_DIM + tid];
            __threadfence();
        }
        __syncthreads();
        if (tid == 0) atomicAdd(&g_count, 1);
    }

    // --- phase 3: string cosine partials, both candidates ---
    {
        int j = tid & 255;
        float* sc = scal + 4 * half;
        float pd = 0.f, p1 = 0.f, p2 = 0.f;
        if (j < DS) {
            float x1 = str_t1[j];
            float x2 = str_t2s[(c0 + half) * DS + j];
            pd = x1 * x2; p1 = x1 * x1; p2 = x2 * x2;
        }
#pragma unroll
        for (int off = 16; off; off >>= 1) {
            pd += __shfl_down_sync(0xffffffffu, pd, off);
            p1 += __shfl_down_sync(0xffffffffu, p1, off);
            p2 += __shfl_down_sync(0xffffffffu, p2, off);
        }
        if (lane == 0 && wloc < 7) {
            atomicAdd(&sc[0], pd);
            atomicAdd(&sc[1], p1);
            atomicAdd(&sc[2], p2);
        }
    }

    // --- phase 4: wait producers, one 32KB bulk copy of AM (shared) ---
    if (tid == 0) {
        while (((volatile int*)&g_count)[0] < K_CTX) {}
        __threadfence();
        asm volatile("fence.proxy.async;" ::: "memory");
        bulk_g2s(smem_u32(sAM), g_AM, K_CTX * D_DIM * 4, mbar_a);
    }
    mbar_wait(mbar_g0, 0);
    mbar_wait(mbar_g1, 0);
    mbar_wait(mbar_a, 0);
    __syncthreads();

    // --- phase 6: sim = tanh(AM @ B^T), CONCURRENT per half.
    // warp wloc -> k rows 8*wloc..+7; lane -> m cols l, l+32.
    {
        float* sB = half ? sB1 : sB0;
        float* rs = rowsum + 64 * half;
        float* cs = colsum + 64 * half;
        const ulonglong2* amp = (const ulonglong2*)(sAM + (wloc * 8) * D_DIM);
        const ulonglong2* b0p = (const ulonglong2*)(sB + lane * SB_STRIDE);
        const ulonglong2* b1p = (const ulonglong2*)(sB + (lane + 32) * SB_STRIDE);
        const int AROW = D_DIM / 4;   // ulonglong2 per A row = 32

        unsigned long long a0c0 = 0, a0c1 = 0, a1c0 = 0, a1c1 = 0;
        unsigned long long a2c0 = 0, a2c1 = 0, a3c0 = 0, a3c1 = 0;
        unsigned long long a4c0 = 0, a4c1 = 0, a5c0 = 0, a5c1 = 0;
        unsigned long long a6c0 = 0, a6c1 = 0, a7c0 = 0, a7c1 = 0;

#pragma unroll 2
        for (int jv = 0; jv < D_DIM / 4; jv++) {
            ulonglong2 vb0 = b0p[jv];
            ulonglong2 vb1 = b1p[jv];
            ulonglong2 a0 = amp[jv];
            ulonglong2 a1 = amp[AROW + jv];
            ulonglong2 a2 = amp[2 * AROW + jv];
            ulonglong2 a3 = amp[3 * AROW + jv];
            a0c0 = ffma2(a0.x, vb0.x, a0c0); a0c0 = ffma2(a0.y, vb0.y, a0c0);
            a0c1 = ffma2(a0.x, vb1.x, a0c1); a0c1 = ffma2(a0.y, vb1.y, a0c1);
            a1c0 = ffma2(a1.x, vb0.x, a1c0); a1c0 = ffma2(a1.y, vb0.y, a1c0);
            a1c1 = ffma2(a1.x, vb1.x, a1c1); a1c1 = ffma2(a1.y, vb1.y, a1c1);
            a2c0 = ffma2(a2.x, vb0.x, a2c0); a2c0 = ffma2(a2.y, vb0.y, a2c0);
            a2c1 = ffma2(a2.x, vb1.x, a2c1); a2c1 = ffma2(a2.y, vb1.y, a2c1);
            a3c0 = ffma2(a3.x, vb0.x, a3c0); a3c0 = ffma2(a3.y, vb0.y, a3c0);
            a3c1 = ffma2(a3.x, vb1.x, a3c1); a3c1 = ffma2(a3.y, vb1.y, a3c1);
            ulonglong2 a4 = amp[4 * AROW + jv];
            ulonglong2 a5 = amp[5 * AROW + jv];
            ulonglong2 a6 = amp[6 * AROW + jv];
            ulonglong2 a7 = amp[7 * AROW + jv];
            a4c0 = ffma2(a4.x, vb0.x, a4c0); a4c0 = ffma2(a4.y, vb0.y, a4c0);
            a4c1 = ffma2(a4.x, vb1.x, a4c1); a4c1 = ffma2(a4.y, vb1.y, a4c1);
            a5c0 = ffma2(a5.x, vb0.x, a5c0); a5c0 = ffma2(a5.y, vb0.y, a5c0);
            a5c1 = ffma2(a5.x, vb1.x, a5c1); a5c1 = ffma2(a5.y, vb1.y, a5c1);
            a6c0 = ffma2(a6.x, vb0.x, a6c0); a6c0 = ffma2(a6.y, vb0.y, a6c0);
            a6c1 = ffma2(a6.x, vb1.x, a6c1); a6c1 = ffma2(a6.y, vb1.y, a6c1);
            a7c0 = ffma2(a7.x, vb0.x, a7c0); a7c0 = ffma2(a7.y, vb0.y, a7c0);
            a7c1 = ffma2(a7.x, vb1.x, a7c1); a7c1 = ffma2(a7.y, vb1.y, a7c1);
        }

        float s0a = tanh_fast(f32x2_hsum(a0c0)), s0b = tanh_fast(f32x2_hsum(a0c1));
        float s1a = tanh_fast(f32x2_hsum(a1c0)), s1b = tanh_fast(f32x2_hsum(a1c1));
        float s2a = tanh_fast(f32x2_hsum(a2c0)), s2b = tanh_fast(f32x2_hsum(a2c1));
        float s3a = tanh_fast(f32x2_hsum(a3c0)), s3b = tanh_fast(f32x2_hsum(a3c1));
        float s4a = tanh_fast(f32x2_hsum(a4c0)), s4b = tanh_fast(f32x2_hsum(a4c1));
        float s5a = tanh_fast(f32x2_hsum(a5c0)), s5b = tanh_fast(f32x2_hsum(a5c1));
        float s6a = tanh_fast(f32x2_hsum(a6c0)), s6b = tanh_fast(f32x2_hsum(a6c1));
        float s7a = tanh_fast(f32x2_hsum(a7c0)), s7b = tanh_fast(f32x2_hsum(a7c1));

        // rowsum: warp covers all 64 m -> shfl reduce 8 values
        float r0 = s0a + s0b, r1 = s1a + s1b, r2 = s2a + s2b, r3 = s3a + s3b;
        float r4 = s4a + s4b, r5 = s5a + s5b, r6 = s6a + s6b, r7 = s7a + s7b;
#pragma unroll
        for (int off = 16; off; off >>= 1) {
            r0 += __shfl_xor_sync(0xffffffffu, r0, off);
            r1 += __shfl_xor_sync(0xffffffffu, r1, off);
            r2 += __shfl_xor_sync(0xffffffffu, r2, off);
            r3 += __shfl_xor_sync(0xffffffffu, r3, off);
            r4 += __shfl_xor_sync(0xffffffffu, r4, off);
            r5 += __shfl_xor_sync(0xffffffffu, r5, off);
            r6 += __shfl_xor_sync(0xffffffffu, r6, off);
            r7 += __shfl_xor_sync(0xffffffffu, r7, off);
        }
        if (lane == 0) {
            rs[wloc * 8 + 0] = r0; rs[wloc * 8 + 1] = r1;
            rs[wloc * 8 + 2] = r2; rs[wloc * 8 + 3] = r3;
            rs[wloc * 8 + 4] = r4; rs[wloc * 8 + 5] = r5;
            rs[wloc * 8 + 6] = r6; rs[wloc * 8 + 7] = r7;
        }
        // colsum: partial over this warp's 8 k-rows (distinct banks per lane)
        atomicAdd(&cs[lane],      s0a + s1a + s2a + s3a + s4a + s5a + s6a + s7a);
        atomicAdd(&cs[lane + 32], s0b + s1b + s2b + s3b + s4b + s5b + s6b + s7b);
    }
    __syncthreads();

    // --- phase 7: 4 softmaxes (c0 rows, c0 cols, c1 rows, c1 cols) ---
    if (tid < 128) {
        int g = tid >> 5;                  // 0..3
        int hh = g >> 1;                   // candidate
        const float* src = (g & 1) ? (colsum + 64 * hh) : (rowsum + 64 * hh);
        float* dst       = (g & 1) ? (cols_w + 64 * hh) : (rows_w + 64 * hh);
        int l = tid & 31;
        float v0 = src[l]      * (1.f / 64.f);
        float v1 = src[l + 32] * (1.f / 64.f);
        float mx = fmaxf(v0, v1);
#pragma unroll
        for (int off = 16; off; off >>= 1)
            mx = fmaxf(mx, __shfl_xor_sync(0xffffffffu, mx, off));
        float e0 = __expf(v0 - mx);
        float e1 = __expf(v1 - mx);
        float s = e0 + e1;
#pragma unroll
        for (int off = 16; off; off >>= 1)
            s += __shfl_xor_sync(0xffffffffu, s, off);
        float inv = 1.f / s;
        dst[l]      = e0 * inv;
        dst[l + 32] = e1 * inv;
    }
    __syncthreads();

    // --- phase 8: new_A / new_B, 256 threads per candidate (2-way k split) ---
    {
        const int t = tid & 255;
        const int d = t & 127;
        const int q = t >> 7;              // k range [32q, 32q+32)
        float* sB = half ? sB1 : sB0;
        const float* rw = rows_w + 64 * half;
        const float* cw = cols_w + 64 * half;
        float na = 0.f, nb = 0.f;
        const float* gA = g_A + (q * 32) * D_DIM + d;
        const float* sb = sB + (q * 32) * SB_STRIDE + d;
#pragma unroll 8
        for (int k = 0; k < 32; k++) {
            na = fmaf(rw[q * 32 + k], __ldg(gA + k * D_DIM), na);
            nb = fmaf(cw[q * 32 + k], sb[k * SB_STRIDE], nb);
        }
        scratch[half * 256 + q * 128 + d]       = na;
        scratch[512 + half * 256 + q * 128 + d] = nb;
    }
    __syncthreads();
    {
        const int t = tid & 255;
        if (t < D_DIM) {
            newA[half * 128 + t] = scratch[half * 256 + t] + scratch[half * 256 + 128 + t];
            newB[half * 128 + t] = scratch[512 + half * 256 + t]
                                 + scratch[512 + half * 256 + 128 + t];
        }
    }
    __syncthreads();

    // --- phase 9: con = newA @ W @ newB + b (2-way d split per candidate) ---
    {
        const int t = tid & 255;
        const int e = t & 127;
        const int q = t >> 7;              // d range [64q, 64q+64)
        const float* wp = W + (q * 64) * D_DIM + e;
        const float* ap = newA + half * 128 + q * 64;
        float s1 = 0.f;
#pragma unroll 8
        for (int d = 0; d < 64; d++)
            s1 = fmaf(ap[d], wp[d * D_DIM], s1);
        scratch[half * 256 + q * 128 + e] = s1;
    }
    __syncthreads();
    {
        const int t = tid & 255;
        if (t < D_DIM) {
            float s1 = scratch[half * 256 + t] + scratch[half * 256 + 128 + t];
            float pc = s1 * newB[half * 128 + t];
#pragma unroll
            for (int off = 16; off; off >>= 1)
                pc += __shfl_down_sync(0xffffffffu, pc, off);
            if (lane == 0) atomicAdd(&scal[4 * half + 3], pc);
        }
    }
    __syncthreads();

    if ((tid & 255) == 0) {
        float* sc = scal + 4 * half;
        float n1 = fmaxf(sqrtf(sc[1]), EPS);
        float n2 = fmaxf(sqrtf(sc[2]), EPS);
        float str_score = sc[0] / (n1 * n2);
        float con_score = sc[3] + b_bi[0];
        out[c0 + half] = 0.5f * str_score + 0.5f * con_score;
    }

    // --- counter reset for graph replay ---
    if (tid == 0) {
        __threadfence();
        int d = atomicAdd(&g_done, 1);
        if (d == GRID_B - 1) {
            g_done  = 0;
            g_count = 0;
        }
    }
}

// ---------------------------------------------------------------------------
extern "C" void kernel_launch(void* const* d_in, const int* in_sizes, int n_in,
                              void* d_out, int out_size) {
    const float* table   = (const float*)d_in[0];
    const float* str_t1  = (const float*)d_in[1];
    const float* str_t2s = (const float*)d_in[2];
    const float* att_mat = (const float*)d_in[3];
    const float* W_bi    = (const float*)d_in[4];
    const float* b_bi    = (const float*)d_in[5];
    const int*   t1_ctx  = (const int*)d_in[6];
    const int*   t2_ctx  = (const int*)d_in[7];
    float* out = (float*)d_out;

    cudaFuncSetAttribute(cand_kernel,
                         cudaFuncAttributeMaxDynamicSharedMemorySize,
                         SMEM_FLOATS * sizeof(float));

    cand_kernel<<<GRID_B, 512, SMEM_FLOATS * sizeof(float)>>>(
        table, str_t1, str_t2s, att_mat, W_bi, b_bi, t1_ctx, t2_ctx, out);
}

// round 11
// speedup vs baseline: 1.0976x; 1.0976x over previous
#include <cuda_runtime.h>
#include <math.h>
#include <stdint.h>

#define K_CTX 64
#define D_DIM 128
#define C_CAND 256
#define DS 200
#define EPS 1e-8f

// Scratch (device globals; no allocation allowed)
__device__ __align__(16) float g_A[K_CTX * D_DIM];
__device__ __align__(16) float g_AM[K_CTX * D_DIM];

// sB row stride 140 floats (560B, 16B aligned): LDS.128 conflict-free
#define SB_STRIDE 140
#define SB_ROW_BYTES (SB_STRIDE * 4)   // 560
#define SMEM_FLOATS (8192 + K_CTX * SB_STRIDE + 4 * 64 + 2 * 128 + 4 + 4)

__device__ __forceinline__ uint32_t smem_u32(const void* p) {
    return (uint32_t)__cvta_generic_to_shared(p);
}
__device__ __forceinline__ void mbar_init(uint32_t mbar, uint32_t cnt) {
    asm volatile("mbarrier.init.shared.b64 [%0], %1;" :: "r"(mbar), "r"(cnt) : "memory");
}
__device__ __forceinline__ void mbar_expect_tx(uint32_t mbar, uint32_t bytes) {
    asm volatile("mbarrier.arrive.expect_tx.shared.b64 _, [%0], %1;"
                 :: "r"(mbar), "r"(bytes) : "memory");
}
__device__ __forceinline__ void mbar_wait(uint32_t mbar, uint32_t parity) {
    uint32_t done;
    asm volatile(
        "{\n\t.reg .pred p;\n\t"
        "mbarrier.try_wait.parity.acquire.cta.shared::cta.b64 p, [%1], %2;\n\t"
        "selp.b32 %0, 1, 0, p;\n\t}"
        : "=r"(done) : "r"(mbar), "r"(parity) : "memory");
    if (!done) {
        asm volatile(
            "{\n\t.reg .pred P1;\n\t"
            "WAIT_LOOP_%=:\n\t"
            "mbarrier.try_wait.parity.acquire.cta.shared::cta.b64 P1, [%0], %1, 0x989680;\n\t"
            "@P1 bra.uni WAIT_DONE_%=;\n\t"
            "bra.uni WAIT_LOOP_%=;\n\t"
            "WAIT_DONE_%=:\n\t}"
            :: "r"(mbar), "r"(parity) : "memory");
    }
}
__device__ __forceinline__ void bulk_g2s(uint32_t dst_smem, const void* src_gmem,
                                         uint32_t bytes, uint32_t mbar) {
    asm volatile(
        "cp.async.bulk.shared::cluster.global.mbarrier::complete_tx::bytes "
        "[%0], [%1], %2, [%3];"
        :: "r"(dst_smem), "l"(src_gmem), "r"(bytes), "r"(mbar) : "memory");
}
__device__ __forceinline__ float tanh_fast(float x) {
    float y;
    asm("tanh.approx.f32 %0, %1;" : "=f"(y) : "f"(x));
    return y;
}
__device__ __forceinline__ unsigned long long ffma2(unsigned long long a,
                                                    unsigned long long b,
                                                    unsigned long long c) {
    unsigned long long d;
    asm("fma.rn.f32x2 %0, %1, %2, %3;" : "=l"(d) : "l"(a), "l"(b), "l"(c));
    return d;
}
__device__ __forceinline__ float f32x2_hsum(unsigned long long v) {
    float lo = __uint_as_float((unsigned)(v & 0xffffffffull));
    float hi = __uint_as_float((unsigned)(v >> 32));
    return lo + hi;
}

// ---------------------------------------------------------------------------
// Kernel 1: prep — grid 64, block 512. Block k computes A row k and AM row k.
// 4-way e-split keeps all 512 threads busy; ~2us total.
// ---------------------------------------------------------------------------
__global__ __launch_bounds__(512, 2)
void prep_kernel(const float* __restrict__ table,
                 const float* __restrict__ att_mat,
                 const int* __restrict__ t1_ctx) {
    __shared__ float arow[D_DIM];
    __shared__ float part[512];
    const int k   = blockIdx.x;
    const int tid = threadIdx.x;

    if (tid < D_DIM) {
        float a = table[(long long)t1_ctx[k] * D_DIM + tid];
        arow[tid] = a;
        g_A[k * D_DIM + tid] = a;
    }
    __syncthreads();
    {
        const int d = tid & 127;
        const int q = tid >> 7;
        const float* att = att_mat + (q * 32) * D_DIM + d;
        const float* ar  = arow + q * 32;
        float acc = 0.f;
#pragma unroll
        for (int e = 0; e < 32; e++)
            acc = fmaf(ar[e], att[e * D_DIM], acc);
        part[tid] = acc;
    }
    __syncthreads();
    if (tid < D_DIM)
        g_AM[k * D_DIM + tid] = part[tid] + part[D_DIM + tid]
                              + part[2 * D_DIM + tid] + part[3 * D_DIM + tid];
}

// ---------------------------------------------------------------------------
// Kernel 2: main — grid 256 (one block per candidate), block 512, 3/SM.
// No producer, no spin: graph edge guarantees g_A/g_AM are ready, so the AM
// bulk copy is issued at phase 0 together with the B gathers.
// ---------------------------------------------------------------------------
__global__ __launch_bounds__(512, 3)
void cand_kernel(const float* __restrict__ table,
                 const float* __restrict__ str_t1,
                 const float* __restrict__ str_t2s,
                 const float* __restrict__ W,     // W_bi[0]: [128,128]
                 const float* __restrict__ b_bi,
                 const int* __restrict__ t2_ctx,
                 float* __restrict__ out) {
    extern __shared__ __align__(16) float sm[];
    float* sAM    = sm;                        // 64*128 (tail scratch too)
    float* sB     = sAM + K_CTX * D_DIM;       // 64*140
    float* rowsum = sB + K_CTX * SB_STRIDE;    // 64
    float* colsum = rowsum + K_CTX;            // 64
    float* rows_w = colsum + K_CTX;            // 64
    float* cols_w = rows_w + K_CTX;            // 64
    float* newA   = cols_w + K_CTX;            // 128
    float* newB   = newA + D_DIM;              // 128
    float* scal   = newB + D_DIM;              // 4
    uint64_t* mbars = (uint64_t*)(scal + 4);   // [0]=gather, [1]=sAM stage

    const int c    = blockIdx.x;
    const int tid  = threadIdx.x;
    const int wid  = tid >> 5;                 // 0..15
    const int lane = tid & 31;
    const uint32_t mbar_g = smem_u32(&mbars[0]);
    const uint32_t mbar_a = smem_u32(&mbars[1]);

    // --- phase 0: init mbarriers + zero accumulators ---
    if (tid == 0) {
        mbar_init(mbar_g, 1);
        mbar_init(mbar_a, 1);
        mbar_expect_tx(mbar_g, K_CTX * D_DIM * 4);
        mbar_expect_tx(mbar_a, K_CTX * D_DIM * 4);
    }
    if (tid < K_CTX) colsum[tid] = 0.f;
    if (tid < 4) scal[tid] = 0.f;
    __syncthreads();   // mbar init visible before complete_tx can land

    // --- phase 1: issue ALL async copies up front ---
    const int* ctx = t2_ctx + c * K_CTX;
    if (tid < K_CTX) {
        bulk_g2s(smem_u32(sB) + tid * SB_ROW_BYTES,
                 table + (long long)ctx[tid] * D_DIM,
                 D_DIM * 4, mbar_g);
    } else if (tid == K_CTX) {
        bulk_g2s(smem_u32(sAM), g_AM, K_CTX * D_DIM * 4, mbar_a);
    }

    // --- phase 2: string cosine partials (hide transfer latency) ---
    {
        float pd = 0.f, p1 = 0.f, p2 = 0.f;
        if (tid < DS) {
            float x1 = str_t1[tid];
            float x2 = str_t2s[c * DS + tid];
            pd = x1 * x2; p1 = x1 * x1; p2 = x2 * x2;
        }
#pragma unroll
        for (int off = 16; off; off >>= 1) {
            pd += __shfl_down_sync(0xffffffffu, pd, off);
            p1 += __shfl_down_sync(0xffffffffu, p1, off);
            p2 += __shfl_down_sync(0xffffffffu, p2, off);
        }
        if (lane == 0 && wid < 7) {
            atomicAdd(&scal[0], pd);
            atomicAdd(&scal[1], p1);
            atomicAdd(&scal[2], p2);
        }
    }

    // --- phase 3: wait both bulk transfers, then block barrier ---
    mbar_wait(mbar_g, 0);
    mbar_wait(mbar_a, 0);
    __syncthreads();

    // --- phase 4: sim = tanh(AM @ B^T) with packed f32x2 FMAs ---
    // warp w -> k rows 4w..4w+3; lane -> m cols l, l+32.
    {
        const ulonglong2* am0 = (const ulonglong2*)(sAM + (wid * 4 + 0) * D_DIM);
        const ulonglong2* am1 = (const ulonglong2*)(sAM + (wid * 4 + 1) * D_DIM);
        const ulonglong2* am2 = (const ulonglong2*)(sAM + (wid * 4 + 2) * D_DIM);
        const ulonglong2* am3 = (const ulonglong2*)(sAM + (wid * 4 + 3) * D_DIM);
        const ulonglong2* b0p = (const ulonglong2*)(sB + lane * SB_STRIDE);
        const ulonglong2* b1p = (const ulonglong2*)(sB + (lane + 32) * SB_STRIDE);

        unsigned long long acc00 = 0, acc01 = 0;
        unsigned long long acc10 = 0, acc11 = 0;
        unsigned long long acc20 = 0, acc21 = 0;
        unsigned long long acc30 = 0, acc31 = 0;

#pragma unroll 4
        for (int jv = 0; jv < D_DIM / 4; jv++) {
            ulonglong2 a0 = am0[jv];
            ulonglong2 a1 = am1[jv];
            ulonglong2 a2 = am2[jv];
            ulonglong2 a3 = am3[jv];
            ulonglong2 b0 = b0p[jv];
            ulonglong2 b1 = b1p[jv];

            acc00 = ffma2(a0.x, b0.x, acc00); acc00 = ffma2(a0.y, b0.y, acc00);
            acc01 = ffma2(a0.x, b1.x, acc01); acc01 = ffma2(a0.y, b1.y, acc01);
            acc10 = ffma2(a1.x, b0.x, acc10); acc10 = ffma2(a1.y, b0.y, acc10);
            acc11 = ffma2(a1.x, b1.x, acc11); acc11 = ffma2(a1.y, b1.y, acc11);
            acc20 = ffma2(a2.x, b0.x, acc20); acc20 = ffma2(a2.y, b0.y, acc20);
            acc21 = ffma2(a2.x, b1.x, acc21); acc21 = ffma2(a2.y, b1.y, acc21);
            acc30 = ffma2(a3.x, b0.x, acc30); acc30 = ffma2(a3.y, b0.y, acc30);
            acc31 = ffma2(a3.x, b1.x, acc31); acc31 = ffma2(a3.y, b1.y, acc31);
        }

        float s00 = tanh_fast(f32x2_hsum(acc00)), s01 = tanh_fast(f32x2_hsum(acc01));
        float s10 = tanh_fast(f32x2_hsum(acc10)), s11 = tanh_fast(f32x2_hsum(acc11));
        float s20 = tanh_fast(f32x2_hsum(acc20)), s21 = tanh_fast(f32x2_hsum(acc21));
        float s30 = tanh_fast(f32x2_hsum(acc30)), s31 = tanh_fast(f32x2_hsum(acc31));

        float r0 = s00 + s01;
        float r1 = s10 + s11;
        float r2 = s20 + s21;
        float r3 = s30 + s31;
#pragma unroll
        for (int off = 16; off; off >>= 1) {
            r0 += __shfl_xor_sync(0xffffffffu, r0, off);
            r1 += __shfl_xor_sync(0xffffffffu, r1, off);
            r2 += __shfl_xor_sync(0xffffffffu, r2, off);
            r3 += __shfl_xor_sync(0xffffffffu, r3, off);
        }
        if (lane == 0) {
            rowsum[wid * 4 + 0] = r0;
            rowsum[wid * 4 + 1] = r1;
            rowsum[wid * 4 + 2] = r2;
            rowsum[wid * 4 + 3] = r3;
        }
        atomicAdd(&colsum[lane],      s00 + s10 + s20 + s30);
        atomicAdd(&colsum[lane + 32], s01 + s11 + s21 + s31);
    }
    __syncthreads();

    // --- phase 5: softmax over 64: warp 0 -> rows, warp 1 -> cols ---
    if (tid < 64) {
        const float* src = (tid < 32) ? rowsum : colsum;
        float* dst       = (tid < 32) ? rows_w : cols_w;
        int l = tid & 31;
        float v0 = src[l]      * (1.f / 64.f);
        float v1 = src[l + 32] * (1.f / 64.f);
        float mx = fmaxf(v0, v1);
#pragma unroll
        for (int off = 16; off; off >>= 1)
            mx = fmaxf(mx, __shfl_xor_sync(0xffffffffu, mx, off));
        float e0 = __expf(v0 - mx);
        float e1 = __expf(v1 - mx);
        float s = e0 + e1;
#pragma unroll
        for (int off = 16; off; off >>= 1)
            s += __shfl_xor_sync(0xffffffffu, s, off);
        float inv = 1.f / s;
        dst[l]      = e0 * inv;
        dst[l + 32] = e1 * inv;
    }
    __syncthreads();

    // --- phase 6: new_A / new_B with all 512 threads (4-way k partials) ---
    {
        const int d = tid & 127;
        const int q = tid >> 7;            // k range [16q, 16q+16)
        float na = 0.f, nb = 0.f;
        const float* gA = g_A + (q * 16) * D_DIM + d;
        const float* sb = sB + (q * 16) * SB_STRIDE + d;
#pragma unroll
        for (int k = 0; k < 16; k++) {
            na = fmaf(rows_w[q * 16 + k], __ldg(gA + k * D_DIM), na);
            nb = fmaf(cols_w[q * 16 + k], sb[k * SB_STRIDE], nb);
        }
        sAM[tid]       = na;               // sAM free after sim: partial scratch
        sAM[512 + tid] = nb;
    }
    __syncthreads();
    if (tid < D_DIM) {
        newA[tid] = sAM[tid] + sAM[128 + tid] + sAM[256 + tid] + sAM[384 + tid];
        newB[tid] = sAM[512 + tid] + sAM[640 + tid] + sAM[768 + tid] + sAM[896 + tid];
    }
    __syncthreads();

    // --- phase 7: con = newA @ W @ newB + b (4-way d partials) ---
    {
        const int e = tid & 127;
        const int q = tid >> 7;            // d range [32q, 32q+32)
        const float* wp = W + (q * 32) * D_DIM + e;
        const float* ap = newA + q * 32;
        float s1 = 0.f;
#pragma unroll
        for (int d = 0; d < 32; d++)
            s1 = fmaf(ap[d], wp[d * D_DIM], s1);
        sAM[tid] = s1;
    }
    __syncthreads();
    if (tid < D_DIM) {
        float s1 = sAM[tid] + sAM[128 + tid] + sAM[256 + tid] + sAM[384 + tid];
        float pc = s1 * newB[tid];
#pragma unroll
        for (int off = 16; off; off >>= 1)
            pc += __shfl_down_sync(0xffffffffu, pc, off);
        if (lane == 0) atomicAdd(&scal[3], pc);
    }
    __syncthreads();

    if (tid == 0) {
        float n1 = fmaxf(sqrtf(scal[1]), EPS);
        float n2 = fmaxf(sqrtf(scal[2]), EPS);
        float str_score = scal[0] / (n1 * n2);
        float con_score = scal[3] + b_bi[0];
        out[c] = 0.5f * str_score + 0.5f * con_score;
    }
}

// ---------------------------------------------------------------------------
extern "C" void kernel_launch(void* const* d_in, const int* in_sizes, int n_in,
                              void* d_out, int out_size) {
    const float* table   = (const float*)d_in[0];
    const float* str_t1  = (const float*)d_in[1];
    const float* str_t2s = (const float*)d_in[2];
    const float* att_mat = (const float*)d_in[3];
    const float* W_bi    = (const float*)d_in[4];
    const float* b_bi    = (const float*)d_in[5];
    const int*   t1_ctx  = (const int*)d_in[6];
    const int*   t2_ctx  = (const int*)d_in[7];
    float* out = (float*)d_out;

    cudaFuncSetAttribute(cand_kernel,
                         cudaFuncAttributeMaxDynamicSharedMemorySize,
                         SMEM_FLOATS * sizeof(float));

    prep_kernel<<<K_CTX, 512>>>(table, att_mat, t1_ctx);
    cand_kernel<<<C_CAND, 512, SMEM_FLOATS * sizeof(float)>>>(
        table, str_t1, str_t2s, W_bi, b_bi, t2_ctx, out);
}